// round 10
// baseline (speedup 1.0000x reference)
#include <cuda_runtime.h>
#include <cuda_fp16.h>
#include <math.h>
#include <stdint.h>

// Problem constants
#define Bb   4
#define Ss   2048
#define HIDn 1024
#define HEADS 16
#define HD   64
#define ROWS (Bb*Ss)          // 8192
#define QKV_STRIDE (Bb*HEADS*Ss*HD)   // 8388608

// softmax scale folded into Q: 0.125 * log2(e)
#define SCALE_Q 0.1803368801111244f

// ---------------- scratch (device globals: allocation-guard safe) ----------
__device__ __half g_QKV[3*QKV_STRIDE];   // [3][B,H,S,D] fp16 (Q pre-scaled)
__device__ __half g_O[Bb*Ss*HIDn];       // [B,S,H*D] fp16
__device__ __half g_WT4[4*HIDn*HIDn];    // 4 transposed+rounded weights [N][K]
__device__ __half g_A3[3*ROWS*HIDn];     // rounded activation copies

// ============================================================================
// helpers
// ============================================================================
__device__ __forceinline__ uint32_t smem_u32(const void* p) {
    uint32_t a;
    asm("{ .reg .u64 t; cvta.to.shared.u64 t, %1; cvt.u32.u64 %0, t; }"
        : "=r"(a) : "l"(p));
    return a;
}
__device__ __forceinline__ void mma16(float& d0, float& d1, float& d2, float& d3,
                                      uint32_t a0, uint32_t a1, uint32_t a2, uint32_t a3,
                                      uint32_t b0, uint32_t b1) {
    asm volatile(
        "mma.sync.aligned.m16n8k16.row.col.f32.f16.f16.f32 "
        "{%0,%1,%2,%3}, {%4,%5,%6,%7}, {%8,%9}, {%0,%1,%2,%3};"
        : "+f"(d0), "+f"(d1), "+f"(d2), "+f"(d3)
        : "r"(a0), "r"(a1), "r"(a2), "r"(a3), "r"(b0), "r"(b1));
}
__device__ __forceinline__ void ldm4(uint32_t& r0, uint32_t& r1, uint32_t& r2,
                                     uint32_t& r3, uint32_t addr) {
    asm volatile("ldmatrix.sync.aligned.m8n8.x4.shared.b16 {%0,%1,%2,%3}, [%4];"
                 : "=r"(r0), "=r"(r1), "=r"(r2), "=r"(r3) : "r"(addr));
}
__device__ __forceinline__ void ldm4t(uint32_t& r0, uint32_t& r1, uint32_t& r2,
                                      uint32_t& r3, uint32_t addr) {
    asm volatile("ldmatrix.sync.aligned.m8n8.x4.trans.shared.b16 {%0,%1,%2,%3}, [%4];"
                 : "=r"(r0), "=r"(r1), "=r"(r2), "=r"(r3) : "r"(addr));
}
__device__ __forceinline__ void cp16(uint32_t s, const void* g) {
    asm volatile("cp.async.cg.shared.global [%0], [%1], 16;" :: "r"(s), "l"(g));
}
__device__ __forceinline__ float ex2(float x) {
    float r;
    asm("ex2.approx.ftz.f32 %0, %1;" : "=f"(r) : "f"(x));
    return r;
}
#define CP_COMMIT() asm volatile("cp.async.commit_group;" ::: "memory")
#define CP_WAIT1()  asm volatile("cp.async.wait_group 1;"  ::: "memory")
#define CP_WAIT0()  asm volatile("cp.async.wait_group 0;"  ::: "memory")

// ============================================================================
// fp16 rounding prepass, 3 tensors in one launch (grid.y selects tensor)
// ============================================================================
__global__ __launch_bounds__(256)
void round_fp16_3(const float4* __restrict__ i0, const float4* __restrict__ i1,
                  const float4* __restrict__ i2, __half2* __restrict__ out)
{
    const int z = blockIdx.y;
    const float4* in = (z == 0) ? i0 : (z == 1) ? i1 : i2;
    const int i = blockIdx.x * 256 + threadIdx.x;
    float4 v = in[i];
    __half2* o = out + (size_t)z * (ROWS * HIDn / 2);
    o[2 * i]     = __floats2half2_rn(v.x, v.y);
    o[2 * i + 1] = __floats2half2_rn(v.z, v.w);
}

// ============================================================================
// Weight transpose + fp16 rounding, 4 weights in one launch (grid.z)
// ============================================================================
__global__ __launch_bounds__(256)
void transpose1024_4(const float* __restrict__ w0, const float* __restrict__ w1,
                     const float* __restrict__ w2, const float* __restrict__ w3,
                     __half* __restrict__ out4)
{
    __shared__ float t[32][33];
    const int z = blockIdx.z;
    const float* in = (z == 0) ? w0 : (z == 1) ? w1 : (z == 2) ? w2 : w3;
    __half* out = out4 + (size_t)z * HIDn * HIDn;
    int x = blockIdx.x * 32 + threadIdx.x;
    int y0 = blockIdx.y * 32;
    #pragma unroll
    for (int l = 0; l < 32; l += 8)
        t[threadIdx.y + l][threadIdx.x] = in[(size_t)(y0 + threadIdx.y + l) * 1024 + x];
    __syncthreads();
    int xo = blockIdx.y * 32 + threadIdx.x;
    int yo = blockIdx.x * 32;
    #pragma unroll
    for (int l = 0; l < 32; l += 8)
        out[(size_t)(yo + threadIdx.y + l) * 1024 + xo] =
            __float2half_rn(t[threadIdx.x][threadIdx.y + l]);
}

// ============================================================================
// fp16 mma.sync GEMM core (128x128 tile, BK=64, 3-stage cp.async, 2 CTAs/SM)
// ============================================================================
#define GSTR_B   144                   // bytes per smem row (64 halves + pad)
#define GSTG_B   (128*GSTR_B)          // 18432 bytes per stage per tensor
#define GEMM_SMEM (2*3*GSTG_B)         // 110592 bytes

struct GemmCore {
    uint32_t sA, sB;
    int tid, wid, lane, gr, tc, wm, wn;
    uint32_t aOff[4], bOff[2];
    int lr, lc;
    float acc[4][4][4];

    __device__ __forceinline__ void init(char* smc) {
        sA = smem_u32(smc);
        sB = sA + 3 * GSTG_B;
        tid = threadIdx.x; wid = tid >> 5; lane = tid & 31;
        gr = lane >> 2; tc = lane & 3;
        const int m8 = lane >> 3, e8 = lane & 7;
        wm = wid & 1; wn = wid >> 1;
        const int lrow = e8 + ((m8 & 1) << 3);
        const int lcolB = (m8 >> 1) << 4;
        #pragma unroll
        for (int mt = 0; mt < 4; mt++)
            aOff[mt] = (uint32_t)((wm * 64 + mt * 16 + lrow) * GSTR_B + lcolB);
        #pragma unroll
        for (int p = 0; p < 2; p++)
            bOff[p] = (uint32_t)((wn * 32 + p * 16 + lrow) * GSTR_B + lcolB);
        #pragma unroll
        for (int mt = 0; mt < 4; mt++)
            #pragma unroll
            for (int nt = 0; nt < 4; nt++)
                #pragma unroll
                for (int e = 0; e < 4; e++) acc[mt][nt][e] = 0.f;
        lr = tid >> 3; lc = tid & 7;
    }
    __device__ __forceinline__ void load_stage(int st, int chunk,
                                               const __half* Ag0, const __half* Bg0) {
        const __half* Ag = Ag0 + chunk * 64;
        const __half* Bg = Bg0 + chunk * 64;
        uint32_t aS = sA + st * GSTG_B;
        uint32_t bS = sB + st * GSTG_B;
        #pragma unroll
        for (int l = 0; l < 4; l++) {
            int r = lr + l * 32;
            cp16(aS + r * GSTR_B + lc * 16, Ag + (size_t)r * 1024 + lc * 8);
            cp16(bS + r * GSTR_B + lc * 16, Bg + (size_t)r * 1024 + lc * 8);
        }
    }
    __device__ __forceinline__ void run(const __half* Ag0, const __half* Bg0) {
        load_stage(0, 0, Ag0, Bg0); CP_COMMIT();
        load_stage(1, 1, Ag0, Bg0); CP_COMMIT();
        for (int i = 0; i < 16; i++) {
            const int s = i % 3;
            CP_WAIT1();
            __syncthreads();
            const int j = i + 2;
            if (j < 16) { load_stage(j % 3, j, Ag0, Bg0); }
            CP_COMMIT();
            const uint32_t aBs = sA + s * GSTG_B;
            const uint32_t bBs = sB + s * GSTG_B;
            #pragma unroll
            for (int ks = 0; ks < 4; ks++) {
                uint32_t a[4][4], b[4][2];
                #pragma unroll
                for (int mt = 0; mt < 4; mt++)
                    ldm4(a[mt][0], a[mt][1], a[mt][2], a[mt][3],
                         aBs + aOff[mt] + ks * 32);
                #pragma unroll
                for (int p = 0; p < 2; p++) {
                    uint32_t t0, t1, t2, t3;
                    ldm4(t0, t1, t2, t3, bBs + bOff[p] + ks * 32);
                    b[2 * p][0]     = t0; b[2 * p][1]     = t2;
                    b[2 * p + 1][0] = t1; b[2 * p + 1][1] = t3;
                }
                #pragma unroll
                for (int mt = 0; mt < 4; mt++)
                    #pragma unroll
                    for (int nt = 0; nt < 4; nt++)
                        mma16(acc[mt][nt][0], acc[mt][nt][1], acc[mt][nt][2], acc[mt][nt][3],
                              a[mt][0], a[mt][1], a[mt][2], a[mt][3], b[nt][0], b[nt][1]);
            }
        }
    }
};

// QKV projections fused: grid (8, 64, 3). Q output pre-scaled by SCALE_Q.
__global__ __launch_bounds__(256, 2)
void gemm_qkv(const __half* __restrict__ A3, const __half* __restrict__ WT4,
              const float* __restrict__ bq, const float* __restrict__ bk,
              const float* __restrict__ bv, __half* __restrict__ QKV)
{
    extern __shared__ __align__(16) char smc[];
    const int z = blockIdx.z;
    const float* bias = (z == 0) ? bq : (z == 1) ? bk : bv;
    const float scale = (z == 0) ? SCALE_Q : 1.0f;
    const int row0 = blockIdx.y * 128;
    const int col0 = blockIdx.x * 128;

    GemmCore g; g.init(smc);
    g.run(A3  + (size_t)z * ROWS * HIDn + (size_t)row0 * 1024,
          WT4 + (size_t)z * HIDn * HIDn + (size_t)col0 * 1024);

    __half* C = QKV + (size_t)z * QKV_STRIDE;
    #pragma unroll
    for (int mt = 0; mt < 4; mt++) {
        const int r0 = row0 + g.wm * 64 + mt * 16 + g.gr;
        #pragma unroll
        for (int nt = 0; nt < 4; nt++) {
            const int c = col0 + g.wn * 32 + nt * 8 + 2 * g.tc;
            const float2 bi = *(const float2*)(bias + c);
            float v00 = (g.acc[mt][nt][0] + bi.x) * scale;
            float v01 = (g.acc[mt][nt][1] + bi.y) * scale;
            float v10 = (g.acc[mt][nt][2] + bi.x) * scale;
            float v11 = (g.acc[mt][nt][3] + bi.y) * scale;
            const int h = c >> 6, d = c & 63;
            {
                const int b = r0 >> 11, s_ = r0 & 2047;
                *(__half2*)(C + ((((size_t)(b * HEADS + h)) * Ss + s_) * HD + d))
                    = __floats2half2_rn(v00, v01);
            }
            {
                const int r1 = r0 + 8;
                const int b = r1 >> 11, s_ = r1 & 2047;
                *(__half2*)(C + ((((size_t)(b * HEADS + h)) * Ss + s_) * HD + d))
                    = __floats2half2_rn(v10, v11);
            }
        }
    }
}

// Output projection: C fp32 row-major.
__global__ __launch_bounds__(256, 2)
void gemm_out(const __half* __restrict__ A, const __half* __restrict__ WT,
              const float* __restrict__ bias, float* __restrict__ C)
{
    extern __shared__ __align__(16) char smc[];
    const int row0 = blockIdx.y * 128;
    const int col0 = blockIdx.x * 128;

    GemmCore g; g.init(smc);
    g.run(A + (size_t)row0 * 1024, WT + (size_t)col0 * 1024);

    #pragma unroll
    for (int mt = 0; mt < 4; mt++) {
        const int r0 = row0 + g.wm * 64 + mt * 16 + g.gr;
        #pragma unroll
        for (int nt = 0; nt < 4; nt++) {
            const int c = col0 + g.wn * 32 + nt * 8 + 2 * g.tc;
            const float2 bi = *(const float2*)(bias + c);
            *(float2*)(C + (size_t)r0 * 1024 + c) =
                make_float2(g.acc[mt][nt][0] + bi.x, g.acc[mt][nt][1] + bi.y);
            *(float2*)(C + (size_t)(r0 + 8) * 1024 + c) =
                make_float2(g.acc[mt][nt][2] + bi.x, g.acc[mt][nt][3] + bi.y);
        }
    }
}

// ============================================================================
// Flash attention, fp16 mma.sync, exp2-domain softmax, software-pipelined:
// per kt: QK0, QK1, softmax0+P0, PV0, softmax1+P1, PV1 — straight-line so
// scalar softmax chains interleave with adjacent HMMA blocks.
// P has TWO smem regions (one per half) to remove WAR hazards.
// Block = (bh, 128-query tile), 256 threads / 8 warps, 2 CTAs/SM.
// ============================================================================
#define ASTR_B   144
#define ATILE_B  (128*ASTR_B)
#define KB_OFF   0
#define VB_OFF   (2*ATILE_B)
#define PS_OFF   (4*ATILE_B)
#define ATT_SMEM_BYTES (6*ATILE_B)          // 110592

__global__ __launch_bounds__(256, 2)
void attn_kernel()
{
    extern __shared__ __align__(16) char smc[];
    const uint32_t sBase = smem_u32(smc);
    const uint32_t sKB = sBase + KB_OFF;
    const uint32_t sVB = sBase + VB_OFF;
    const uint32_t sPS = sBase + PS_OFF;

    const int bh   = blockIdx.y;
    const int qt   = blockIdx.x;
    const int tid  = threadIdx.x;
    const int wid  = tid >> 5;
    const int lane = tid & 31;
    const int gr   = lane >> 2;
    const int tc   = lane & 3;
    const int m8   = lane >> 3;
    const int e8   = lane & 7;

    const __half* Qg = g_QKV + (size_t)bh * Ss * HD + (size_t)qt * 128 * HD;
    const __half* Kg = g_QKV + QKV_STRIDE     + (size_t)bh * Ss * HD;
    const __half* Vg = g_QKV + 2 * QKV_STRIDE + (size_t)bh * Ss * HD;

    const int lr = tid >> 3;
    const int lc = tid & 7;

    #define LOAD_KV(kt) do {                                                    \
        const __half* _Kt = Kg + (size_t)(kt) * 128 * HD;                       \
        const __half* _Vt = Vg + (size_t)(kt) * 128 * HD;                       \
        uint32_t _kS = sKB + ((kt) & 1) * ATILE_B;                              \
        uint32_t _vS = sVB + ((kt) & 1) * ATILE_B;                              \
        _Pragma("unroll")                                                       \
        for (int l = 0; l < 4; l++) {                                           \
            int r = lr + l * 32;                                                \
            cp16(_kS + r * ASTR_B + lc * 16, _Kt + (size_t)r * HD + lc * 8);    \
            cp16(_vS + r * ASTR_B + lc * 16, _Vt + (size_t)r * HD + lc * 8);    \
        }                                                                       \
    } while (0)

    LOAD_KV(0); CP_COMMIT();

    // stage Q (pre-scaled) into P region 0, extract persistent fragments
    {
        __half* Pq = (__half*)(smc + PS_OFF);
        #pragma unroll
        for (int l = 0; l < 4; l++) {
            int r = lr + l * 32;
            *(uint4*)((char*)Pq + r * ASTR_B + lc * 16) =
                *(const uint4*)(Qg + (size_t)r * HD + lc * 8);
        }
    }
    __syncthreads();
    const int lrow = e8 + ((m8 & 1) << 3);
    const int lcolB = (m8 >> 1) << 4;
    uint32_t qf[4][4];
    {
        const uint32_t qbase = sPS + (uint32_t)((wid * 16 + lrow) * ASTR_B + lcolB);
        #pragma unroll
        for (int ks = 0; ks < 4; ks++)
            ldm4(qf[ks][0], qf[ks][1], qf[ks][2], qf[ks][3], qbase + ks * 32);
    }

    uint32_t kOff[4];
    #pragma unroll
    for (int p = 0; p < 4; p++)
        kOff[p] = (uint32_t)((p * 16 + lrow) * ASTR_B + lcolB);
    const uint32_t vOff = (uint32_t)(lrow * ASTR_B + lcolB);
    const uint32_t pLdBase = sPS + (uint32_t)(wid * 16 * ASTR_B + lrow * ASTR_B + lcolB);
    __half* pSt0 = (__half*)(smc + PS_OFF) + (wid * 16 + gr) * 72 + 2 * tc;
    __half* pSt1 = pSt0 + 8 * 72;

    float m0 = -1e30f, m1 = -1e30f, l0 = 0.f, l1 = 0.f;
    float o[8][4];
    #pragma unroll
    for (int nt = 0; nt < 8; nt++)
        #pragma unroll
        for (int e = 0; e < 4; e++) o[nt][e] = 0.f;

    for (int kt = 0; kt < 16; kt++) {
        CP_WAIT0();
        __syncthreads();

        if (kt < 15) { LOAD_KV(kt + 1); CP_COMMIT(); }

        const uint32_t kb = sKB + (kt & 1) * ATILE_B;
        const uint32_t vb = sVB + (kt & 1) * ATILE_B;

        // ---- QK for BOTH halves up front (128 keys of scores) ----
        float sacc[2][8][4];
        #pragma unroll
        for (int h = 0; h < 2; h++)
            #pragma unroll
            for (int nt = 0; nt < 8; nt++)
                #pragma unroll
                for (int e = 0; e < 4; e++) sacc[h][nt][e] = 0.f;

        #pragma unroll
        for (int h = 0; h < 2; h++) {
            const uint32_t kbh = kb + h * (64 * ASTR_B);
            #pragma unroll
            for (int ks = 0; ks < 4; ks++) {
                #pragma unroll
                for (int p = 0; p < 4; p++) {
                    uint32_t t0, t1, t2, t3;
                    ldm4(t0, t1, t2, t3, kbh + kOff[p] + ks * 32);
                    mma16(sacc[h][2 * p][0], sacc[h][2 * p][1],
                          sacc[h][2 * p][2], sacc[h][2 * p][3],
                          qf[ks][0], qf[ks][1], qf[ks][2], qf[ks][3], t0, t2);
                    mma16(sacc[h][2 * p + 1][0], sacc[h][2 * p + 1][1],
                          sacc[h][2 * p + 1][2], sacc[h][2 * p + 1][3],
                          qf[ks][0], qf[ks][1], qf[ks][2], qf[ks][3], t1, t3);
                }
            }
        }

        // ---- per half: softmax + P store + PV (straight-line, overlappable)
        #pragma unroll
        for (int h = 0; h < 2; h++) {
            float (*sa)[4] = sacc[h];
            float mx0 = -1e30f, mx1 = -1e30f;
            #pragma unroll
            for (int nt = 0; nt < 8; nt++) {
                mx0 = fmaxf(mx0, fmaxf(sa[nt][0], sa[nt][1]));
                mx1 = fmaxf(mx1, fmaxf(sa[nt][2], sa[nt][3]));
            }
            mx0 = fmaxf(mx0, __shfl_xor_sync(0xFFFFFFFFu, mx0, 1));
            mx0 = fmaxf(mx0, __shfl_xor_sync(0xFFFFFFFFu, mx0, 2));
            mx1 = fmaxf(mx1, __shfl_xor_sync(0xFFFFFFFFu, mx1, 1));
            mx1 = fmaxf(mx1, __shfl_xor_sync(0xFFFFFFFFu, mx1, 2));
            const float mn0 = fmaxf(m0, mx0), mn1 = fmaxf(m1, mx1);
            const float c0 = ex2(m0 - mn0), c1 = ex2(m1 - mn1);
            float s0 = 0.f, s1 = 0.f;
            #pragma unroll
            for (int nt = 0; nt < 8; nt++) {
                sa[nt][0] = ex2(sa[nt][0] - mn0);
                sa[nt][1] = ex2(sa[nt][1] - mn0);
                sa[nt][2] = ex2(sa[nt][2] - mn1);
                sa[nt][3] = ex2(sa[nt][3] - mn1);
                s0 += sa[nt][0] + sa[nt][1];
                s1 += sa[nt][2] + sa[nt][3];
            }
            s0 += __shfl_xor_sync(0xFFFFFFFFu, s0, 1);
            s0 += __shfl_xor_sync(0xFFFFFFFFu, s0, 2);
            s1 += __shfl_xor_sync(0xFFFFFFFFu, s1, 1);
            s1 += __shfl_xor_sync(0xFFFFFFFFu, s1, 2);
            l0 = l0 * c0 + s0;  l1 = l1 * c1 + s1;
            m0 = mn0;           m1 = mn1;
            #pragma unroll
            for (int nt = 0; nt < 8; nt++) {
                o[nt][0] *= c0; o[nt][1] *= c0;
                o[nt][2] *= c1; o[nt][3] *= c1;
            }

            // stage P half h into its own region
            __half* p0 = pSt0 + h * (ATILE_B / 2);   // halves offset (bytes/2)
            __half* p1 = pSt1 + h * (ATILE_B / 2);
            #pragma unroll
            for (int nt = 0; nt < 8; nt++) {
                *(__half2*)(p0 + nt * 8) = __floats2half2_rn(sa[nt][0], sa[nt][1]);
                *(__half2*)(p1 + nt * 8) = __floats2half2_rn(sa[nt][2], sa[nt][3]);
            }
            __syncwarp();

            // PV for half h
            const uint32_t vbh = vb + h * (64 * ASTR_B);
            const uint32_t pB  = pLdBase + h * ATILE_B;
            #pragma unroll
            for (int kp = 0; kp < 4; kp++) {
                uint32_t a0, a1, a2, a3;
                ldm4(a0, a1, a2, a3, pB + kp * 32);
                #pragma unroll
                for (int np = 0; np < 4; np++) {
                    uint32_t t0, t1, t2, t3;
                    ldm4t(t0, t1, t2, t3, vbh + vOff + kp * (16 * ASTR_B) + np * 32);
                    mma16(o[2 * np][0], o[2 * np][1], o[2 * np][2], o[2 * np][3],
                          a0, a1, a2, a3, t0, t1);
                    mma16(o[2 * np + 1][0], o[2 * np + 1][1],
                          o[2 * np + 1][2], o[2 * np + 1][3],
                          a0, a1, a2, a3, t2, t3);
                }
            }
        }
    }

    // ---- normalize + store to g_O [B,S,H*D] fp16 ----
    const float i0 = 1.0f / l0;
    const float i1 = 1.0f / l1;
    const int b  = bh >> 4;
    const int hh = bh & 15;
    const int r0 = wid * 16 + gr;
    #pragma unroll
    for (int nt = 0; nt < 8; nt++) {
        const int d = nt * 8 + 2 * tc;
        {
            const int s_ = qt * 128 + r0;
            size_t idx = ((size_t)(b * Ss + s_)) * HIDn + hh * HD + d;
            *(__half2*)(g_O + idx) = __floats2half2_rn(o[nt][0] * i0, o[nt][1] * i0);
        }
        {
            const int s_ = qt * 128 + r0 + 8;
            size_t idx = ((size_t)(b * Ss + s_)) * HIDn + hh * HD + d;
            *(__half2*)(g_O + idx) = __floats2half2_rn(o[nt][2] * i1, o[nt][3] * i1);
        }
    }
}

// ============================================================================
// launch
// ============================================================================
extern "C" void kernel_launch(void* const* d_in, const int* in_sizes, int n_in,
                              void* d_out, int out_size)
{
    (void)in_sizes; (void)n_in; (void)out_size;
    const float* q  = (const float*)d_in[0];
    const float* k  = (const float*)d_in[1];
    const float* v  = (const float*)d_in[2];
    const float* wq = (const float*)d_in[3];
    const float* bq = (const float*)d_in[4];
    const float* wk = (const float*)d_in[5];
    const float* bk = (const float*)d_in[6];
    const float* wv = (const float*)d_in[7];
    const float* bv = (const float*)d_in[8];
    const float* wo = (const float*)d_in[9];
    const float* bo = (const float*)d_in[10];
    float* out = (float*)d_out;

    __half *QKVp, *Op, *WT4p, *A3p;
    cudaGetSymbolAddress((void**)&QKVp, g_QKV);
    cudaGetSymbolAddress((void**)&Op,   g_O);
    cudaGetSymbolAddress((void**)&WT4p, g_WT4);
    cudaGetSymbolAddress((void**)&A3p,  g_A3);

    cudaFuncSetAttribute(attn_kernel,
                         cudaFuncAttributeMaxDynamicSharedMemorySize, ATT_SMEM_BYTES);
    cudaFuncSetAttribute(gemm_qkv,
                         cudaFuncAttributeMaxDynamicSharedMemorySize, GEMM_SMEM);
    cudaFuncSetAttribute(gemm_out,
                         cudaFuncAttributeMaxDynamicSharedMemorySize, GEMM_SMEM);

    const int rblocks = ROWS * HIDn / 4 / 256;   // 8192

    transpose1024_4<<<dim3(32, 32, 4), dim3(32, 8)>>>(wq, wk, wv, wo, WT4p);
    round_fp16_3<<<dim3(rblocks, 3), 256>>>((const float4*)q, (const float4*)k,
                                            (const float4*)v, (__half2*)A3p);

    gemm_qkv<<<dim3(8, 64, 3), 256, GEMM_SMEM>>>(A3p, WT4p, bq, bk, bv, QKVp);

    attn_kernel<<<dim3(Ss / 128, Bb * HEADS), 256, ATT_SMEM_BYTES>>>();

    gemm_out<<<dim3(8, 64), 256, GEMM_SMEM>>>(Op, WT4p + 3 * (size_t)HIDn * HIDn,
                                              bo, out);
}